// round 4
// baseline (speedup 1.0000x reference)
#include <cuda_runtime.h>
#include <math.h>

#define T_LEN     1048576
#define MAXO      25
#define CLAMP_HI  24.0f
#define SEG       8
#define NTHREADS  256
#define NWARP     (NTHREADS/32)
#define PER_BLOCK (SEG*NTHREADS)     /* 2048 */
#define NB        (T_LEN/PER_BLOCK)  /* 512  */
#define FULLM     0xffffffffu

struct Fn { float a, b, c; };

__device__ Fn    g_agg[NB];
__device__ float g_prefval[NB];
__device__ int   g_status[NB];   // 0 = invalid, 1 = aggregate, 2 = inclusive prefix

__device__ __forceinline__ Fn fn_identity() { return Fn{0.f, -1e30f, 1e30f}; }

// f1 applied first, then f2:  (f2 o f1)(x) = min(max(x+a, b), c)
__device__ __forceinline__ Fn fn_compose(Fn f1, Fn f2) {
    Fn r;
    r.a = f1.a + f2.a;
    r.b = fmaxf(f1.b + f2.a, f2.b);
    r.c = fminf(fmaxf(f1.c + f2.a, f2.b), f2.c);
    return r;
}

__device__ __forceinline__ float fn_apply(Fn f, float x) {
    return fminf(fmaxf(x + f.a, f.b), f.c);
}

__device__ __forceinline__ int ld_acquire(const int* p) {
    int v;
    asm volatile("ld.acquire.gpu.global.b32 %0, [%1];" : "=r"(v) : "l"(p) : "memory");
    return v;
}
__device__ __forceinline__ void st_release(int* p, int v) {
    asm volatile("st.release.gpu.global.b32 [%0], %1;" :: "l"(p), "r"(v) : "memory");
}

__device__ __forceinline__ Fn warp_incl_scan(Fn v, int lane) {
    #pragma unroll
    for (int off = 1; off < 32; off <<= 1) {
        float pa = __shfl_up_sync(FULLM, v.a, off);
        float pb = __shfl_up_sync(FULLM, v.b, off);
        float pc = __shfl_up_sync(FULLM, v.c, off);
        if (lane >= off) v = fn_compose(Fn{pa, pb, pc}, v);
    }
    return v;
}

// suffix-compose across a warp: result at lane 0 = compose(lane31 first, ..., lane0 last)
__device__ __forceinline__ Fn warp_suffix_compose(Fn w, int lane) {
    #pragma unroll
    for (int off = 1; off < 32; off <<= 1) {
        Fn u;
        u.a = __shfl_down_sync(FULLM, w.a, off);
        u.b = __shfl_down_sync(FULLM, w.b, off);
        u.c = __shfl_down_sync(FULLM, w.c, off);
        if (lane + off < 32) w = fn_compose(u, w);   // higher lane = earlier tile = applied first
    }
    return w;
}

// ---------------------------------------------------------------------------
__global__ void k_init() {
    g_status[threadIdx.x] = 0;
}

// ---------------------------------------------------------------------------
__global__ void __launch_bounds__(NTHREADS)
k_main(const int* __restrict__ seq, const float* __restrict__ delta,
       const float* __restrict__ bias, const float* __restrict__ scale,
       float* __restrict__ out) {
    __shared__ float dl[16];
    __shared__ float An[MAXO], Ap[MAXO];
    __shared__ Fn    warpTot[NWARP];
    __shared__ Fn    s_agg;
    __shared__ float s_start;
    __shared__ __align__(16) float cnt[NTHREADS * (SEG + 1)];  // stride 9 rows
    __shared__ __align__(16) float stage[NTHREADS * MAXO];     // 8 warps x 800 floats

    int tid = threadIdx.x, lane = tid & 31, wid = tid >> 5, bid = blockIdx.x;
    float s = scale[0];
    if (tid < 16) dl[tid] = delta[tid];
    if (tid < MAXO) {
        float fj = (float)tid;
        An[tid] = expf(bias[tid] - s * fj);   // j >= c  path  (* e^{ s c})
        Ap[tid] = expf(bias[tid] + s * fj);   // j <  c  path  (* e^{-s c})
    }
    __syncthreads();

    // ---- load 8 symbols / thread, build thread clamp-function ----
    const int4* p = (const int4*)(seq + (size_t)bid * PER_BLOCK + tid * SEG);
    int4 v0 = p[0], v1 = p[1];
    int vals[8] = {v0.x, v0.y, v0.z, v0.w, v1.x, v1.y, v1.z, v1.w};
    float dv[8];

    Fn f = fn_identity();
    #pragma unroll
    for (int i = 0; i < 8; i++) {
        float d = dl[vals[i]];
        dv[i] = d;
        f.a += d;
        f.b = fmaxf(f.b + d, 0.f);
        f.c = fminf(fmaxf(f.c + d, 0.f), CLAMP_HI);
    }

    // ---- block scan of thread functions ----
    Fn inc = warp_incl_scan(f, lane);
    if (lane == 31) warpTot[wid] = inc;
    __syncthreads();

    // publish block aggregate ASAP (tid 0)
    if (tid == 0) {
        Fn t = warpTot[0];
        #pragma unroll
        for (int w = 1; w < NWARP; w++) t = fn_compose(t, warpTot[w]);
        s_agg = t;
        if (bid > 0) {
            g_agg[bid] = t;
            __threadfence();
            st_release(&g_status[bid], 1);
        }
    }
    __syncwarp();  // s_agg visible within warp 0

    // ---- decoupled lookback (warp 0) ----
    if (wid == 0) {
        float start = 0.f;
        if (bid > 0) {
            Fn ex = fn_identity();
            int base = bid - 1;
            for (;;) {
                int idx = base - lane;
                int st; Fn v = fn_identity(); float pv = 0.f;
                if (idx < 0) {
                    st = 2; pv = 0.f;
                } else {
                    do { st = ld_acquire(&g_status[idx]); } while (st == 0);
                    if (st == 1) {
                        v.a = __ldcg(&g_agg[idx].a);
                        v.b = __ldcg(&g_agg[idx].b);
                        v.c = __ldcg(&g_agg[idx].c);
                    } else {
                        pv = __ldcg(&g_prefval[idx]);
                    }
                }
                unsigned pmask = __ballot_sync(FULLM, st == 2);
                if (pmask) {
                    int lp = __ffs(pmask) - 1;               // nearest prefix tile
                    Fn w = (lane < lp) ? v : fn_identity();  // aggregates after the prefix tile
                    w = warp_suffix_compose(w, lane);
                    float pvp = __shfl_sync(FULLM, pv, lp);
                    Fn w0;
                    w0.a = __shfl_sync(FULLM, w.a, 0);
                    w0.b = __shfl_sync(FULLM, w.b, 0);
                    w0.c = __shfl_sync(FULLM, w.c, 0);
                    Fn tot = fn_compose(w0, ex);             // window first, then older ex
                    start = fn_apply(tot, pvp);
                    break;
                } else {
                    Fn w = warp_suffix_compose(v, lane);
                    Fn w0;
                    w0.a = __shfl_sync(FULLM, w.a, 0);
                    w0.b = __shfl_sync(FULLM, w.b, 0);
                    w0.c = __shfl_sync(FULLM, w.c, 0);
                    ex = fn_compose(w0, ex);
                    base -= 32;
                }
            }
        }
        if (lane == 0) {
            s_start = start;
            float incl = fn_apply(s_agg, start);
            g_prefval[bid] = incl;
            __threadfence();
            st_release(&g_status[bid], 2);
        }
    }
    __syncthreads();
    float start = s_start;

    // ---- per-thread exclusive prefix, exact local recurrence ----
    Fn wexcl = fn_identity();
    for (int w = 0; w < wid; w++) wexcl = fn_compose(wexcl, warpTot[w]);
    float pa = __shfl_up_sync(FULLM, inc.a, 1);
    float pb = __shfl_up_sync(FULLM, inc.b, 1);
    float pc = __shfl_up_sync(FULLM, inc.c, 1);
    Fn lane_excl = (lane == 0) ? fn_identity() : Fn{pa, pb, pc};
    Fn excl = fn_compose(wexcl, lane_excl);

    float c = fn_apply(excl, start);
    #pragma unroll
    for (int i = 0; i < 8; i++) {
        c = fminf(fmaxf(c + dv[i], 0.f), CLAMP_HI);
        cnt[tid * (SEG + 1) + i] = c;
    }
    __syncthreads();

    // ---- per-warp softmax + staged coalesced streaming writes ----
    float* wstage = stage + wid * (32 * MAXO);                 // 800 floats / warp
    size_t outbase = ((size_t)bid * PER_BLOCK + wid * 256) * (size_t)MAXO;

    for (int batch = 0; batch < 8; batch++) {
        int r = wid * 256 + batch * 32 + lane;
        float cc  = cnt[(r >> 3) * (SEG + 1) + (r & 7)];
        float ec  = expf(s * cc);
        float emc = expf(-s * cc);
        float wgt[MAXO];
        float sum = 0.f;
        #pragma unroll
        for (int j = 0; j < MAXO; j++) {
            float wj = ((float)j >= cc) ? An[j] * ec : Ap[j] * emc;
            wgt[j] = wj;
            sum += wj;
        }
        float invs = 1.0f / sum;
        __syncwarp();
        #pragma unroll
        for (int j = 0; j < MAXO; j++) wstage[lane * MAXO + j] = wgt[j] * invs;
        __syncwarp();

        const float4* ss = (const float4*)wstage;
        float4* dd = (float4*)(out + outbase + (size_t)batch * (32 * MAXO));
        #pragma unroll
        for (int k = lane; k < 32 * MAXO / 4; k += 32) __stcs(dd + k, ss[k]);
    }
}

// ---------------------------------------------------------------------------
extern "C" void kernel_launch(void* const* d_in, const int* in_sizes, int n_in,
                              void* d_out, int out_size) {
    const int*   seq   = (const int*)  d_in[0];
    const float* delta = (const float*)d_in[1];
    const float* bias  = (const float*)d_in[2];
    const float* scale = (const float*)d_in[3];
    float* out = (float*)d_out;

    k_init<<<1, NB>>>();
    k_main<<<NB, NTHREADS>>>(seq, delta, bias, scale, out);
}

// round 5
// speedup vs baseline: 1.1282x; 1.1282x over previous
#include <cuda_runtime.h>
#include <math.h>

#define T_LEN     1048576
#define MAXO      25
#define CLAMP_HI  24.0f
#define SEG       8
#define NTHREADS  256
#define NWARP     (NTHREADS/32)
#define PER_BLOCK (SEG*NTHREADS)     /* 2048 */
#define NB        (T_LEN/PER_BLOCK)  /* 512  */
#define FULLM     0xffffffffu

struct Fn { float a, b, c; };

__device__ Fn    g_blockF[NB];
__device__ float g_blockStart[NB];

__device__ __forceinline__ Fn fn_identity() { return Fn{0.f, -1e30f, 1e30f}; }

// f1 applied first, then f2:  (f2 o f1)(x) = min(max(x+a, b), c)
__device__ __forceinline__ Fn fn_compose(Fn f1, Fn f2) {
    Fn r;
    r.a = f1.a + f2.a;
    r.b = fmaxf(f1.b + f2.a, f2.b);
    r.c = fminf(fmaxf(f1.c + f2.a, f2.b), f2.c);
    return r;
}

__device__ __forceinline__ float fn_apply(Fn f, float x) {
    return fminf(fmaxf(x + f.a, f.b), f.c);
}

__device__ __forceinline__ Fn warp_incl_scan(Fn v, int lane) {
    #pragma unroll
    for (int off = 1; off < 32; off <<= 1) {
        float pa = __shfl_up_sync(FULLM, v.a, off);
        float pb = __shfl_up_sync(FULLM, v.b, off);
        float pc = __shfl_up_sync(FULLM, v.c, off);
        if (lane >= off) v = fn_compose(Fn{pa, pb, pc}, v);
    }
    return v;
}

// ---------------------------------------------------------------------------
// K1: per-block composed clamp function
// ---------------------------------------------------------------------------
__global__ void __launch_bounds__(NTHREADS)
k1_block_totals(const int* __restrict__ seq, const float* __restrict__ delta) {
    __shared__ float dl[16];
    __shared__ Fn warpTot[NWARP];
    int tid = threadIdx.x, lane = tid & 31, wid = tid >> 5;
    if (tid < 16) dl[tid] = delta[tid];
    __syncthreads();

    const int4* p = (const int4*)(seq + (size_t)blockIdx.x * PER_BLOCK + tid * SEG);
    int4 v0 = p[0], v1 = p[1];
    int vals[8] = {v0.x, v0.y, v0.z, v0.w, v1.x, v1.y, v1.z, v1.w};

    Fn f = fn_identity();
    #pragma unroll
    for (int i = 0; i < 8; i++) {
        float d = dl[vals[i]];
        f.a += d;
        f.b = fmaxf(f.b + d, 0.f);
        f.c = fminf(fmaxf(f.c + d, 0.f), CLAMP_HI);
    }
    Fn inc = warp_incl_scan(f, lane);
    if (lane == 31) warpTot[wid] = inc;
    __syncthreads();
    if (tid == 0) {
        Fn t = warpTot[0];
        #pragma unroll
        for (int w = 1; w < NWARP; w++) t = fn_compose(t, warpTot[w]);
        g_blockF[blockIdx.x] = t;
    }
}

// ---------------------------------------------------------------------------
// K2: scan the NB=512 block functions -> per-block start counter value
// ---------------------------------------------------------------------------
__global__ void __launch_bounds__(NB)
k2_scan_blocks() {
    __shared__ Fn warpTot[NB / 32];   // 16
    int tid = threadIdx.x, lane = tid & 31, wid = tid >> 5;
    Fn f = g_blockF[tid];
    Fn inc = warp_incl_scan(f, lane);
    if (lane == 31) warpTot[wid] = inc;
    __syncthreads();
    if (wid == 0) {
        Fn v = (lane < NB / 32) ? warpTot[lane] : fn_identity();
        #pragma unroll
        for (int off = 1; off < NB / 32; off <<= 1) {
            float pa = __shfl_up_sync(FULLM, v.a, off);
            float pb = __shfl_up_sync(FULLM, v.b, off);
            float pc = __shfl_up_sync(FULLM, v.c, off);
            if (lane >= off) v = fn_compose(Fn{pa, pb, pc}, v);
        }
        if (lane < NB / 32) warpTot[lane] = v;
    }
    __syncthreads();
    float pa = __shfl_up_sync(FULLM, inc.a, 1);
    float pb = __shfl_up_sync(FULLM, inc.b, 1);
    float pc = __shfl_up_sync(FULLM, inc.c, 1);
    Fn lane_excl = (lane == 0) ? fn_identity() : Fn{pa, pb, pc};
    Fn wexcl     = (wid  == 0) ? fn_identity() : warpTot[wid - 1];
    Fn excl = fn_compose(wexcl, lane_excl);
    g_blockStart[tid] = fn_apply(excl, 0.f);
}

// ---------------------------------------------------------------------------
// K3: counters + factored softmax with suffix-sum normalization,
//     per-warp SMEM staging, coalesced float4 writes, no block barriers
//     in the output loop.
// ---------------------------------------------------------------------------
__global__ void __launch_bounds__(NTHREADS)
k3_output(const int* __restrict__ seq, const float* __restrict__ delta,
          const float* __restrict__ bias, const float* __restrict__ scale,
          float* __restrict__ out) {
    __shared__ float dl[16];
    __shared__ float An[MAXO], Ap[MAXO];
    __shared__ float SufAn[MAXO + 1], PreAp[MAXO + 1];
    __shared__ Fn    warpTot[NWARP];
    __shared__ __align__(16) float cnt[NTHREADS * (SEG + 1)];  // stride 9: low conflict
    __shared__ __align__(16) float stage[NTHREADS * MAXO];     // 8 warps x 800 floats

    int tid = threadIdx.x, lane = tid & 31, wid = tid >> 5, bid = blockIdx.x;
    float s = scale[0];
    if (tid < 16) dl[tid] = delta[tid];
    if (tid < MAXO) {
        float fj = (float)tid;
        An[tid] = expf(bias[tid] - s * fj);   // j >= c  path  (* e^{ s c})
        Ap[tid] = expf(bias[tid] + s * fj);   // j <  c  path  (* e^{-s c})
    }
    __syncthreads();

    // suffix/prefix sums for O(1) softmax normalization (two threads, overlapped
    // with the scan work below via the later __syncthreads)
    if (tid == 0) {
        float a = 0.f;
        SufAn[MAXO] = 0.f;
        for (int k = MAXO - 1; k >= 0; k--) { a += An[k]; SufAn[k] = a; }
    }
    if (tid == 32) {
        float a = 0.f;
        PreAp[0] = 0.f;
        for (int k = 1; k <= MAXO; k++) { a += Ap[k - 1]; PreAp[k] = a; }
    }

    // ---- load 8 symbols / thread, build thread clamp-function ----
    const int4* p = (const int4*)(seq + (size_t)bid * PER_BLOCK + tid * SEG);
    int4 v0 = p[0], v1 = p[1];
    int vals[8] = {v0.x, v0.y, v0.z, v0.w, v1.x, v1.y, v1.z, v1.w};
    float dv[8];

    Fn f = fn_identity();
    #pragma unroll
    for (int i = 0; i < 8; i++) {
        float d = dl[vals[i]];
        dv[i] = d;
        f.a += d;
        f.b = fmaxf(f.b + d, 0.f);
        f.c = fminf(fmaxf(f.c + d, 0.f), CLAMP_HI);
    }

    // ---- block exclusive scan of thread functions ----
    Fn inc = warp_incl_scan(f, lane);
    if (lane == 31) warpTot[wid] = inc;
    __syncthreads();
    if (wid == 0) {
        Fn v = (lane < NWARP) ? warpTot[lane] : fn_identity();
        #pragma unroll
        for (int off = 1; off < NWARP; off <<= 1) {
            float pa = __shfl_up_sync(FULLM, v.a, off);
            float pb = __shfl_up_sync(FULLM, v.b, off);
            float pc = __shfl_up_sync(FULLM, v.c, off);
            if (lane >= off) v = fn_compose(Fn{pa, pb, pc}, v);
        }
        if (lane < NWARP) warpTot[lane] = v;
    }
    __syncthreads();
    float pa = __shfl_up_sync(FULLM, inc.a, 1);
    float pb = __shfl_up_sync(FULLM, inc.b, 1);
    float pc = __shfl_up_sync(FULLM, inc.c, 1);
    Fn lane_excl = (lane == 0) ? fn_identity() : Fn{pa, pb, pc};
    Fn wexcl     = (wid  == 0) ? fn_identity() : warpTot[wid - 1];
    Fn excl = fn_compose(wexcl, lane_excl);

    // ---- exact sequential recurrence within this thread's 8 rows ----
    float c = fn_apply(excl, g_blockStart[bid]);
    #pragma unroll
    for (int i = 0; i < 8; i++) {
        c = fminf(fmaxf(c + dv[i], 0.f), CLAMP_HI);
        cnt[tid * (SEG + 1) + i] = c;
    }
    __syncthreads();

    // ---- per-warp softmax + staged coalesced writes ----
    float* wstage = stage + wid * (32 * MAXO);                 // 800 floats / warp
    size_t outbase = ((size_t)bid * PER_BLOCK + wid * 256) * (size_t)MAXO;

    #pragma unroll 1
    for (int batch = 0; batch < 8; batch++) {
        int r = wid * 256 + batch * 32 + lane;
        float cc  = cnt[(r >> 3) * (SEG + 1) + (r & 7)];
        int   k   = (int)ceilf(cc);                 // j >= cc  <=>  j >= k
        float ec  = __expf(s * cc);
        float emc = __expf(-s * cc);
        float sum = ec * SufAn[k] + emc * PreAp[k];
        float inv = __fdividef(1.0f, sum);
        float eci = ec * inv, emci = emc * inv;
        #pragma unroll
        for (int j = 0; j < MAXO; j++)
            wstage[lane * MAXO + j] = (j >= k) ? An[j] * eci : Ap[j] * emci;
        __syncwarp();

        const float4* ss = (const float4*)wstage;
        float4* dd = (float4*)(out + outbase + (size_t)batch * (32 * MAXO));
        for (int q = lane; q < 32 * MAXO / 4; q += 32) dd[q] = ss[q];
        __syncwarp();
    }
}

// ---------------------------------------------------------------------------
extern "C" void kernel_launch(void* const* d_in, const int* in_sizes, int n_in,
                              void* d_out, int out_size) {
    const int*   seq   = (const int*)  d_in[0];
    const float* delta = (const float*)d_in[1];
    const float* bias  = (const float*)d_in[2];
    const float* scale = (const float*)d_in[3];
    float* out = (float*)d_out;

    k1_block_totals<<<NB, NTHREADS>>>(seq, delta);
    k2_scan_blocks<<<1, NB>>>();
    k3_output<<<NB, NTHREADS>>>(seq, delta, bias, scale, out);
}

// round 6
// speedup vs baseline: 1.2067x; 1.0696x over previous
#include <cuda_runtime.h>
#include <math.h>

#define T_LEN     1048576
#define MAXO      25
#define CLAMP_HI  24.0f
#define SEG       8
#define NTHREADS  256
#define NWARP     (NTHREADS/32)
#define PER_BLOCK (SEG*NTHREADS)       /* 2048 */
#define NB        (T_LEN/PER_BLOCK)    /* 512 tiles */
#define K1_THREADS 512
#define K1_ELEMS   16
#define K1_BLOCKS  (T_LEN/(K1_THREADS*K1_ELEMS))   /* 128 */
#define FULLM     0xffffffffu

struct Fn { float a, b, c; };

__device__ Fn g_blockF[NB];

__device__ __forceinline__ Fn fn_identity() { return Fn{0.f, -1e30f, 1e30f}; }

// f1 applied first, then f2:  (f2 o f1)(x) = min(max(x+a, b), c)
__device__ __forceinline__ Fn fn_compose(Fn f1, Fn f2) {
    Fn r;
    r.a = f1.a + f2.a;
    r.b = fmaxf(f1.b + f2.a, f2.b);
    r.c = fminf(fmaxf(f1.c + f2.a, f2.b), f2.c);
    return r;
}

__device__ __forceinline__ float fn_apply(Fn f, float x) {
    return fminf(fmaxf(x + f.a, f.b), f.c);
}

__device__ __forceinline__ Fn warp_incl_scan(Fn v, int lane) {
    #pragma unroll
    for (int off = 1; off < 32; off <<= 1) {
        float pa = __shfl_up_sync(FULLM, v.a, off);
        float pb = __shfl_up_sync(FULLM, v.b, off);
        float pc = __shfl_up_sync(FULLM, v.c, off);
        if (lane >= off) v = fn_compose(Fn{pa, pb, pc}, v);
    }
    return v;
}

// ---------------------------------------------------------------------------
// K1: 128 blocks x 512 threads, 16 elems/thread -> 4 tile functions per block
// ---------------------------------------------------------------------------
__global__ void __launch_bounds__(K1_THREADS)
k1_block_totals(const int* __restrict__ seq, const float* __restrict__ delta) {
    __shared__ float dl[16];
    __shared__ Fn warpTot[K1_THREADS / 32];   // 16
    int tid = threadIdx.x, lane = tid & 31, wid = tid >> 5;
    if (tid < 16) dl[tid] = delta[tid];
    __syncthreads();

    const int4* p = (const int4*)(seq + (size_t)blockIdx.x * (K1_THREADS * K1_ELEMS)
                                      + tid * K1_ELEMS);
    int4 w0 = p[0], w1 = p[1], w2 = p[2], w3 = p[3];
    int vals[16] = {w0.x, w0.y, w0.z, w0.w, w1.x, w1.y, w1.z, w1.w,
                    w2.x, w2.y, w2.z, w2.w, w3.x, w3.y, w3.z, w3.w};

    Fn f = fn_identity();
    #pragma unroll
    for (int i = 0; i < 16; i++) {
        float d = dl[vals[i]];
        f.a += d;
        f.b = fmaxf(f.b + d, 0.f);
        f.c = fminf(fmaxf(f.c + d, 0.f), CLAMP_HI);
    }
    Fn inc = warp_incl_scan(f, lane);
    if (lane == 31) warpTot[wid] = inc;
    __syncthreads();
    // one warp = 512 elems = quarter tile; tile = 4 consecutive warps
    if (tid < 4) {
        Fn t = warpTot[tid * 4];
        #pragma unroll
        for (int w = 1; w < 4; w++) t = fn_compose(t, warpTot[tid * 4 + w]);
        g_blockF[blockIdx.x * 4 + tid] = t;
    }
}

// ---------------------------------------------------------------------------
// K3: global prefix recompute (block-wide, from L2-hot g_blockF) + counters
//     + factored softmax + per-warp staged coalesced streaming writes.
// ---------------------------------------------------------------------------
__global__ void __launch_bounds__(NTHREADS)
k3_output(const int* __restrict__ seq, const float* __restrict__ delta,
          const float* __restrict__ bias, const float* __restrict__ scale,
          float* __restrict__ out) {
    __shared__ float dl[16];
    __shared__ float An[MAXO], Ap[MAXO];
    __shared__ float SufAn[MAXO + 1], PreAp[MAXO + 1];
    __shared__ Fn    warpTotG[NWARP];
    __shared__ Fn    warpTot[NWARP];
    __shared__ float s_start;
    __shared__ __align__(16) float cnt[NTHREADS * (SEG + 1)];
    __shared__ __align__(16) float stage[NTHREADS * MAXO];

    int tid = threadIdx.x, lane = tid & 31, wid = tid >> 5, bid = blockIdx.x;
    float s = scale[0];
    if (tid < 16) dl[tid] = delta[tid];
    if (tid < MAXO) {
        float fj = (float)tid;
        An[tid] = expf(bias[tid] - s * fj);   // j >= c path (* e^{ s c})
        Ap[tid] = expf(bias[tid] + s * fj);   // j <  c path (* e^{-s c})
    }

    // issue seq loads early
    const int4* p = (const int4*)(seq + (size_t)bid * PER_BLOCK + tid * SEG);
    int4 v0 = p[0], v1 = p[1];

    // load this thread's pair of global tile functions (L2-hot, 6 KB total)
    Fn gA = g_blockF[2 * tid];
    Fn gB = g_blockF[2 * tid + 1];
    __syncthreads();

    if (tid == 0) {
        float a = 0.f;
        SufAn[MAXO] = 0.f;
        for (int k = MAXO - 1; k >= 0; k--) { a += An[k]; SufAn[k] = a; }
    }
    if (tid == 32) {
        float a = 0.f;
        PreAp[0] = 0.f;
        for (int k = 1; k <= MAXO; k++) { a += Ap[k - 1]; PreAp[k] = a; }
    }

    // ---- block-wide scan over the 512 tile functions (2 per thread) ----
    Fn pair = fn_compose(gA, gB);
    Fn incG = warp_incl_scan(pair, lane);
    if (lane == 31) warpTotG[wid] = incG;
    __syncthreads();
    if (wid == 0) {
        Fn v = (lane < NWARP) ? warpTotG[lane] : fn_identity();
        #pragma unroll
        for (int off = 1; off < NWARP; off <<= 1) {
            float pa = __shfl_up_sync(FULLM, v.a, off);
            float pb = __shfl_up_sync(FULLM, v.b, off);
            float pc = __shfl_up_sync(FULLM, v.c, off);
            if (lane >= off) v = fn_compose(Fn{pa, pb, pc}, v);
        }
        if (lane < NWARP) warpTotG[lane] = v;
    }
    __syncthreads();
    {
        float pa = __shfl_up_sync(FULLM, incG.a, 1);
        float pb = __shfl_up_sync(FULLM, incG.b, 1);
        float pc = __shfl_up_sync(FULLM, incG.c, 1);
        Fn lane_excl = (lane == 0) ? fn_identity() : Fn{pa, pb, pc};
        Fn wexcl     = (wid  == 0) ? fn_identity() : warpTotG[wid - 1];
        Fn exclG = fn_compose(wexcl, lane_excl);   // prefix of fns [0, 2*tid)
        if (tid == (bid >> 1)) {
            Fn e = exclG;
            if (bid & 1) e = fn_compose(e, gA);    // add fn[bid-1]
            s_start = fn_apply(e, 0.f);
        }
    }

    // ---- per-thread fn over its 8 symbols ----
    int vals[8] = {v0.x, v0.y, v0.z, v0.w, v1.x, v1.y, v1.z, v1.w};
    float dv[8];
    Fn f = fn_identity();
    #pragma unroll
    for (int i = 0; i < 8; i++) {
        float d = dl[vals[i]];
        dv[i] = d;
        f.a += d;
        f.b = fmaxf(f.b + d, 0.f);
        f.c = fminf(fmaxf(f.c + d, 0.f), CLAMP_HI);
    }

    // ---- block scan of thread functions ----
    Fn inc = warp_incl_scan(f, lane);
    if (lane == 31) warpTot[wid] = inc;
    __syncthreads();                                // also publishes s_start
    if (wid == 0) {
        Fn v = (lane < NWARP) ? warpTot[lane] : fn_identity();
        #pragma unroll
        for (int off = 1; off < NWARP; off <<= 1) {
            float pa = __shfl_up_sync(FULLM, v.a, off);
            float pb = __shfl_up_sync(FULLM, v.b, off);
            float pc = __shfl_up_sync(FULLM, v.c, off);
            if (lane >= off) v = fn_compose(Fn{pa, pb, pc}, v);
        }
        if (lane < NWARP) warpTot[lane] = v;
    }
    __syncthreads();
    float pa = __shfl_up_sync(FULLM, inc.a, 1);
    float pb = __shfl_up_sync(FULLM, inc.b, 1);
    float pc = __shfl_up_sync(FULLM, inc.c, 1);
    Fn lane_excl = (lane == 0) ? fn_identity() : Fn{pa, pb, pc};
    Fn wexcl     = (wid  == 0) ? fn_identity() : warpTot[wid - 1];
    Fn excl = fn_compose(wexcl, lane_excl);

    // ---- exact sequential recurrence within this thread's 8 rows ----
    float c = fn_apply(excl, s_start);
    #pragma unroll
    for (int i = 0; i < 8; i++) {
        c = fminf(fmaxf(c + dv[i], 0.f), CLAMP_HI);
        cnt[tid * (SEG + 1) + i] = c;
    }
    __syncthreads();

    // ---- per-warp softmax + staged coalesced streaming writes ----
    float* wstage = stage + wid * (32 * MAXO);
    size_t outbase = ((size_t)bid * PER_BLOCK + wid * 256) * (size_t)MAXO;

    #pragma unroll 1
    for (int batch = 0; batch < 8; batch++) {
        int r = wid * 256 + batch * 32 + lane;
        float cc  = cnt[(r >> 3) * (SEG + 1) + (r & 7)];
        int   k   = (int)ceilf(cc);
        float ec  = __expf(s * cc);
        float emc = __expf(-s * cc);
        float sum = ec * SufAn[k] + emc * PreAp[k];
        float inv = __fdividef(1.0f, sum);
        float eci = ec * inv, emci = emc * inv;
        #pragma unroll
        for (int j = 0; j < MAXO; j++)
            wstage[lane * MAXO + j] = (j >= k) ? An[j] * eci : Ap[j] * emci;
        __syncwarp();

        const float4* ss = (const float4*)wstage;
        float4* dd = (float4*)(out + outbase + (size_t)batch * (32 * MAXO));
        #pragma unroll
        for (int q = lane; q < 32 * MAXO / 4; q += 32) __stcs(dd + q, ss[q]);
        __syncwarp();
    }
}

// ---------------------------------------------------------------------------
extern "C" void kernel_launch(void* const* d_in, const int* in_sizes, int n_in,
                              void* d_out, int out_size) {
    const int*   seq   = (const int*)  d_in[0];
    const float* delta = (const float*)d_in[1];
    const float* bias  = (const float*)d_in[2];
    const float* scale = (const float*)d_in[3];
    float* out = (float*)d_out;

    k1_block_totals<<<K1_BLOCKS, K1_THREADS>>>(seq, delta);
    k3_output<<<NB, NTHREADS>>>(seq, delta, bias, scale, out);
}

// round 7
// speedup vs baseline: 1.2187x; 1.0099x over previous
#include <cuda_runtime.h>
#include <math.h>

#define T_LEN     1048576
#define MAXO      25
#define CLAMP_HI  24.0f
#define SEG       4
#define NTHREADS  256
#define NWARP     (NTHREADS/32)
#define PER_BLOCK (SEG*NTHREADS)       /* 1024 */
#define NB        (T_LEN/PER_BLOCK)    /* 1024 tiles */
#define K1_THREADS 512
#define K1_ELEMS   16
#define K1_BLOCKS  (T_LEN/(K1_THREADS*K1_ELEMS))   /* 128 */
#define TILES_PER_K1 ((K1_THREADS*K1_ELEMS)/PER_BLOCK)  /* 8 */
#define FPT       (NB/NTHREADS)        /* 4 fns per thread in global scan */
#define FULLM     0xffffffffu

struct Fn { float a, b, c; };

__device__ Fn g_blockF[NB];

__device__ __forceinline__ Fn fn_identity() { return Fn{0.f, -1e30f, 1e30f}; }

// f1 applied first, then f2:  (f2 o f1)(x) = min(max(x+a, b), c)
__device__ __forceinline__ Fn fn_compose(Fn f1, Fn f2) {
    Fn r;
    r.a = f1.a + f2.a;
    r.b = fmaxf(f1.b + f2.a, f2.b);
    r.c = fminf(fmaxf(f1.c + f2.a, f2.b), f2.c);
    return r;
}

__device__ __forceinline__ float fn_apply(Fn f, float x) {
    return fminf(fmaxf(x + f.a, f.b), f.c);
}

__device__ __forceinline__ Fn warp_incl_scan(Fn v, int lane) {
    #pragma unroll
    for (int off = 1; off < 32; off <<= 1) {
        float pa = __shfl_up_sync(FULLM, v.a, off);
        float pb = __shfl_up_sync(FULLM, v.b, off);
        float pc = __shfl_up_sync(FULLM, v.c, off);
        if (lane >= off) v = fn_compose(Fn{pa, pb, pc}, v);
    }
    return v;
}

// ---------------------------------------------------------------------------
// K1: 128 blocks x 512 threads, 16 elems/thread -> 8 tile functions per block
//     (tile = 1024 elems = 2 warps)
// ---------------------------------------------------------------------------
__global__ void __launch_bounds__(K1_THREADS)
k1_block_totals(const int* __restrict__ seq, const float* __restrict__ delta) {
    __shared__ float dl[16];
    __shared__ Fn warpTot[K1_THREADS / 32];   // 16
    int tid = threadIdx.x, lane = tid & 31, wid = tid >> 5;
    if (tid < 16) dl[tid] = delta[tid];
    __syncthreads();

    const int4* p = (const int4*)(seq + (size_t)blockIdx.x * (K1_THREADS * K1_ELEMS)
                                      + tid * K1_ELEMS);
    int4 w0 = p[0], w1 = p[1], w2 = p[2], w3 = p[3];
    int vals[16] = {w0.x, w0.y, w0.z, w0.w, w1.x, w1.y, w1.z, w1.w,
                    w2.x, w2.y, w2.z, w2.w, w3.x, w3.y, w3.z, w3.w};

    Fn f = fn_identity();
    #pragma unroll
    for (int i = 0; i < 16; i++) {
        float d = dl[vals[i]];
        f.a += d;
        f.b = fmaxf(f.b + d, 0.f);
        f.c = fminf(fmaxf(f.c + d, 0.f), CLAMP_HI);
    }
    Fn inc = warp_incl_scan(f, lane);
    if (lane == 31) warpTot[wid] = inc;
    __syncthreads();
    // one warp = 512 elems; one 1024-elem tile = 2 consecutive warps
    if (tid < TILES_PER_K1) {
        Fn t = fn_compose(warpTot[tid * 2], warpTot[tid * 2 + 1]);
        g_blockF[blockIdx.x * TILES_PER_K1 + tid] = t;
    }
}

// ---------------------------------------------------------------------------
// K3: global prefix recompute + counters + factored softmax + per-warp
//     staged coalesced streaming writes.  1024 CTAs for high occupancy.
// ---------------------------------------------------------------------------
__global__ void __launch_bounds__(NTHREADS)
k3_output(const int* __restrict__ seq, const float* __restrict__ delta,
          const float* __restrict__ bias, const float* __restrict__ scale,
          float* __restrict__ out) {
    __shared__ float dl[16];
    __shared__ float An[MAXO], Ap[MAXO];
    __shared__ float SufAn[MAXO + 1], PreAp[MAXO + 1];
    __shared__ Fn    warpTotG[NWARP];
    __shared__ Fn    warpTot[NWARP];
    __shared__ float s_start;
    __shared__ __align__(16) float cnt[NTHREADS * (SEG + 1)];   // 5.1 KB
    __shared__ __align__(16) float stage[NTHREADS * MAXO];      // 25.6 KB

    int tid = threadIdx.x, lane = tid & 31, wid = tid >> 5, bid = blockIdx.x;
    float s = scale[0];
    if (tid < 16) dl[tid] = delta[tid];
    if (tid < MAXO) {
        float fj = (float)tid;
        An[tid] = expf(bias[tid] - s * fj);   // j >= c path (* e^{ s c})
        Ap[tid] = expf(bias[tid] + s * fj);   // j <  c path (* e^{-s c})
    }

    // issue seq loads early
    const int4* p = (const int4*)(seq + (size_t)bid * PER_BLOCK + tid * SEG);
    int4 v0 = p[0];

    // load this thread's FPT=4 global tile functions (L2-hot, 12 KB total)
    Fn g4[FPT];
    #pragma unroll
    for (int i = 0; i < FPT; i++) g4[i] = g_blockF[FPT * tid + i];
    __syncthreads();

    if (tid == 0) {
        float a = 0.f;
        SufAn[MAXO] = 0.f;
        for (int k = MAXO - 1; k >= 0; k--) { a += An[k]; SufAn[k] = a; }
    }
    if (tid == 32) {
        float a = 0.f;
        PreAp[0] = 0.f;
        for (int k = 1; k <= MAXO; k++) { a += Ap[k - 1]; PreAp[k] = a; }
    }

    // ---- block-wide scan over the 1024 tile functions (4 per thread) ----
    Fn quad = g4[0];
    #pragma unroll
    for (int i = 1; i < FPT; i++) quad = fn_compose(quad, g4[i]);
    Fn incG = warp_incl_scan(quad, lane);
    if (lane == 31) warpTotG[wid] = incG;
    __syncthreads();
    if (wid == 0) {
        Fn v = (lane < NWARP) ? warpTotG[lane] : fn_identity();
        #pragma unroll
        for (int off = 1; off < NWARP; off <<= 1) {
            float pa = __shfl_up_sync(FULLM, v.a, off);
            float pb = __shfl_up_sync(FULLM, v.b, off);
            float pc = __shfl_up_sync(FULLM, v.c, off);
            if (lane >= off) v = fn_compose(Fn{pa, pb, pc}, v);
        }
        if (lane < NWARP) warpTotG[lane] = v;
    }
    __syncthreads();
    {
        float pa = __shfl_up_sync(FULLM, incG.a, 1);
        float pb = __shfl_up_sync(FULLM, incG.b, 1);
        float pc = __shfl_up_sync(FULLM, incG.c, 1);
        Fn lane_excl = (lane == 0) ? fn_identity() : Fn{pa, pb, pc};
        Fn wexcl     = (wid  == 0) ? fn_identity() : warpTotG[wid - 1];
        Fn exclG = fn_compose(wexcl, lane_excl);   // prefix of fns [0, FPT*tid)
        if (tid == (bid >> 2)) {
            Fn e = exclG;
            #pragma unroll
            for (int i = 0; i < FPT - 1; i++)
                if (i < (bid & 3)) e = fn_compose(e, g4[i]);
            s_start = fn_apply(e, 0.f);
        }
    }

    // ---- per-thread fn over its 4 symbols ----
    int vals[SEG] = {v0.x, v0.y, v0.z, v0.w};
    float dv[SEG];
    Fn f = fn_identity();
    #pragma unroll
    for (int i = 0; i < SEG; i++) {
        float d = dl[vals[i]];
        dv[i] = d;
        f.a += d;
        f.b = fmaxf(f.b + d, 0.f);
        f.c = fminf(fmaxf(f.c + d, 0.f), CLAMP_HI);
    }

    // ---- block scan of thread functions ----
    Fn inc = warp_incl_scan(f, lane);
    if (lane == 31) warpTot[wid] = inc;
    __syncthreads();                                // also publishes s_start
    if (wid == 0) {
        Fn v = (lane < NWARP) ? warpTot[lane] : fn_identity();
        #pragma unroll
        for (int off = 1; off < NWARP; off <<= 1) {
            float pa = __shfl_up_sync(FULLM, v.a, off);
            float pb = __shfl_up_sync(FULLM, v.b, off);
            float pc = __shfl_up_sync(FULLM, v.c, off);
            if (lane >= off) v = fn_compose(Fn{pa, pb, pc}, v);
        }
        if (lane < NWARP) warpTot[lane] = v;
    }
    __syncthreads();
    float pa = __shfl_up_sync(FULLM, inc.a, 1);
    float pb = __shfl_up_sync(FULLM, inc.b, 1);
    float pc = __shfl_up_sync(FULLM, inc.c, 1);
    Fn lane_excl = (lane == 0) ? fn_identity() : Fn{pa, pb, pc};
    Fn wexcl     = (wid  == 0) ? fn_identity() : warpTot[wid - 1];
    Fn excl = fn_compose(wexcl, lane_excl);

    // ---- exact sequential recurrence within this thread's SEG rows ----
    float c = fn_apply(excl, s_start);
    #pragma unroll
    for (int i = 0; i < SEG; i++) {
        c = fminf(fmaxf(c + dv[i], 0.f), CLAMP_HI);
        cnt[tid * (SEG + 1) + i] = c;
    }
    __syncthreads();

    // ---- per-warp softmax + staged coalesced streaming writes ----
    float* wstage = stage + wid * (32 * MAXO);
    size_t outbase = ((size_t)bid * PER_BLOCK + wid * (PER_BLOCK / NWARP)) * (size_t)MAXO;

    #pragma unroll 1
    for (int batch = 0; batch < PER_BLOCK / NWARP / 32; batch++) {
        int r = wid * (PER_BLOCK / NWARP) + batch * 32 + lane;
        float cc  = cnt[(r >> 2) * (SEG + 1) + (r & 3)];
        int   k   = (int)ceilf(cc);
        float ec  = __expf(s * cc);
        float emc = __expf(-s * cc);
        float sum = ec * SufAn[k] + emc * PreAp[k];
        float inv = __fdividef(1.0f, sum);
        float eci = ec * inv, emci = emc * inv;
        #pragma unroll
        for (int j = 0; j < MAXO; j++)
            wstage[lane * MAXO + j] = (j >= k) ? An[j] * eci : Ap[j] * emci;
        __syncwarp();

        const float4* ss = (const float4*)wstage;
        float4* dd = (float4*)(out + outbase + (size_t)batch * (32 * MAXO));
        #pragma unroll
        for (int q = lane; q < 32 * MAXO / 4; q += 32) __stcs(dd + q, ss[q]);
        __syncwarp();
    }
}

// ---------------------------------------------------------------------------
extern "C" void kernel_launch(void* const* d_in, const int* in_sizes, int n_in,
                              void* d_out, int out_size) {
    const int*   seq   = (const int*)  d_in[0];
    const float* delta = (const float*)d_in[1];
    const float* bias  = (const float*)d_in[2];
    const float* scale = (const float*)d_in[3];
    float* out = (float*)d_out;

    k1_block_totals<<<K1_BLOCKS, K1_THREADS>>>(seq, delta);
    k3_output<<<NB, NTHREADS>>>(seq, delta, bias, scale, out);
}